// round 1
// baseline (speedup 1.0000x reference)
#include <cuda_runtime.h>

// Problem constants
#define BB 16
#define NN 2048
#define KK 10

// Scratch (no allocations allowed)
__device__ int   g_idx[BB * NN * KK];
__device__ float g_loss[BB * NN];

#define K1_BLK 64
#define K2_BLK 64

// ---------------------------------------------------------------------------
// Kernel 1: masked KNN (top-10 smallest d2 with d2 + 1e-7 >= 0.1)
// d2 computed as |x|^2 + |y|^2 - 2 x.y to match the reference einsum formula.
// ---------------------------------------------------------------------------
__global__ void __launch_bounds__(K1_BLK) knn_kernel(const float* __restrict__ src) {
    __shared__ float sx[NN], sy[NN], sz[NN], sq[NN];
    const int blocksPerB = NN / K1_BLK;
    const int b     = blockIdx.x / blocksPerB;
    const int chunk = blockIdx.x % blocksPerB;
    const float* base = src + (size_t)b * 3 * NN;

    for (int i = threadIdx.x; i < NN; i += K1_BLK) {
        float x = base[i];
        float y = base[NN + i];
        float z = base[2 * NN + i];
        sx[i] = x; sy[i] = y; sz[i] = z;
        sq[i] = x * x + y * y + z * z;
    }
    __syncthreads();

    const int n = chunk * K1_BLK + threadIdx.x;
    const float qx = sx[n], qy = sy[n], qz = sz[n], qs = sq[n];
    const float INF = __int_as_float(0x7f800000);

    float d[KK];
    int   id[KK];
#pragma unroll
    for (int j = 0; j < KK; j++) { d[j] = INF; id[j] = -1; }
    float worst = INF;

#pragma unroll 4
    for (int i = 0; i < NN; i++) {
        float dot = qx * sx[i] + qy * sy[i] + qz * sz[i];
        float d2  = qs + sq[i] - 2.0f * dot;
        // reference mask: -(d2+1e-7) > -0.1  =>  excluded
        bool valid = ((d2 + 1e-7f) >= 0.1f);
        if (valid && (d2 < worst)) {
            float cd = d2; int ci = i;
#pragma unroll
            for (int j = 0; j < KK; j++) {
                if (cd < d[j]) {
                    float td = d[j]; d[j] = cd; cd = td;
                    int   ti = id[j]; id[j] = ci; ci = ti;
                }
            }
            worst = d[KK - 1];
        }
    }

    // Fallback: fewer than KK valid neighbors (top_k fills with smallest
    // masked indices, all tied at -inf). Essentially never taken.
    if (id[KK - 1] < 0) {
        int slot = 0;
        while (slot < KK && id[slot] >= 0) slot++;
        for (int i = 0; i < NN && slot < KK; i++) {
            float dot = qx * sx[i] + qy * sy[i] + qz * sz[i];
            float d2  = qs + sq[i] - 2.0f * dot;
            if (!((d2 + 1e-7f) >= 0.1f)) id[slot++] = i;
        }
    }

    int* op = g_idx + ((size_t)(b * NN) + n) * KK;
#pragma unroll
    for (int j = 0; j < KK; j++) op[j] = id[j];
}

// ---------------------------------------------------------------------------
// Kernel 2: 45 triangle pair losses per point, mean of sqrt of 10 smallest
// ---------------------------------------------------------------------------
__device__ __forceinline__ void sort3(float& a, float& b, float& c) {
    float t0 = fminf(a, b), t1 = fmaxf(a, b);
    float hi = fmaxf(t1, c);
    float mm = fminf(t1, c);
    float lo = fminf(t0, mm);
    float mi = fmaxf(t0, mm);
    a = lo; b = mi; c = hi;
}

__global__ void __launch_bounds__(K2_BLK) loss_kernel(const float* __restrict__ src,
                                                      const float* __restrict__ tgt) {
    __shared__ float ssx[NN], ssy[NN], ssz[NN];
    __shared__ float stx[NN], sty[NN], stz[NN];
    const int blocksPerB = NN / K2_BLK;
    const int b     = blockIdx.x / blocksPerB;
    const int chunk = blockIdx.x % blocksPerB;
    const float* sb = src + (size_t)b * 3 * NN;
    const float* tb = tgt + (size_t)b * 3 * NN;

    for (int i = threadIdx.x; i < NN; i += K2_BLK) {
        ssx[i] = sb[i]; ssy[i] = sb[NN + i]; ssz[i] = sb[2 * NN + i];
        stx[i] = tb[i]; sty[i] = tb[NN + i]; stz[i] = tb[2 * NN + i];
    }
    __syncthreads();

    const int n = chunk * K2_BLK + threadIdx.x;
    const int* nb = g_idx + ((size_t)(b * NN) + n) * KK;

    float px[KK + 1], py[KK + 1], pz[KK + 1];
    float tx[KK + 1], ty[KK + 1], tz[KK + 1];
    px[0] = ssx[n]; py[0] = ssy[n]; pz[0] = ssz[n];
    tx[0] = stx[n]; ty[0] = sty[n]; tz[0] = stz[n];
#pragma unroll
    for (int j = 0; j < KK; j++) {
        int m = nb[j];
        px[j + 1] = ssx[m]; py[j + 1] = ssy[m]; pz[j + 1] = ssz[m];
        tx[j + 1] = stx[m]; ty[j + 1] = sty[m]; tz[j + 1] = stz[m];
    }

    const float INF = __int_as_float(0x7f800000);
    float ls[KK];
#pragma unroll
    for (int j = 0; j < KK; j++) ls[j] = INF;
    float worst = INF;

#pragma unroll
    for (int a = 0; a < KK - 1; a++) {
#pragma unroll
        for (int c = a + 1; c < KK; c++) {
            const int ia = a + 1, ic = c + 1;
            float dx, dy, dz;
            // src triangle (direct differences, matching get_tri)
            dx = px[0] - px[ia]; dy = py[0] - py[ia]; dz = pz[0] - pz[ia];
            float s01 = dx * dx + dy * dy + dz * dz;
            dx = px[ia] - px[ic]; dy = py[ia] - py[ic]; dz = pz[ia] - pz[ic];
            float s12 = dx * dx + dy * dy + dz * dz;
            dx = px[0] - px[ic]; dy = py[0] - py[ic]; dz = pz[0] - pz[ic];
            float s02 = dx * dx + dy * dy + dz * dz;
            sort3(s01, s12, s02);
            // tgt triangle
            dx = tx[0] - tx[ia]; dy = ty[0] - ty[ia]; dz = tz[0] - tz[ia];
            float t01 = dx * dx + dy * dy + dz * dz;
            dx = tx[ia] - tx[ic]; dy = ty[ia] - ty[ic]; dz = tz[ia] - tz[ic];
            float t12 = dx * dx + dy * dy + dz * dz;
            dx = tx[0] - tx[ic]; dy = ty[0] - ty[ic]; dz = tz[0] - tz[ic];
            float t02 = dx * dx + dy * dy + dz * dz;
            sort3(t01, t12, t02);
            // EPS added AFTER sorting (matches: get_tri(tgt) + EPS)
            t01 += 1e-6f; t12 += 1e-6f; t02 += 1e-6f;

            float n0 = s01 - t01, n1 = s12 - t12, n2 = s02 - t02;
            float num = n0 * n0 + n1 * n1 + n2 * n2;
            float p0 = s01 + t01, p1 = s12 + t12, p2 = s02 + t02;
            float den = p0 * p0 + p1 * p1 + p2 * p2;
            float L = num / den;

            if (L < worst) {
                float cd = L;
#pragma unroll
                for (int j = 0; j < KK; j++) {
                    if (cd < ls[j]) { float t = ls[j]; ls[j] = cd; cd = t; }
                }
                worst = ls[KK - 1];
            }
        }
    }

    float acc = 0.0f;
#pragma unroll
    for (int j = 0; j < KK; j++) acc += sqrtf(ls[j] + 1e-6f);
    g_loss[b * NN + n] = acc * 0.1f;
}

// ---------------------------------------------------------------------------
// Kernel 3: per-batch min, sigmoid weight, threshold
// ---------------------------------------------------------------------------
__global__ void __launch_bounds__(256) weight_kernel(float* __restrict__ out) {
    const int b   = blockIdx.x;
    const int tid = threadIdx.x;
    const float* lp = g_loss + b * NN;

    float m = __int_as_float(0x7f800000);
    for (int i = tid; i < NN; i += 256) m = fminf(m, lp[i]);
#pragma unroll
    for (int o = 16; o; o >>= 1) m = fminf(m, __shfl_xor_sync(0xffffffffu, m, o));

    __shared__ float wmin[8];
    if ((tid & 31) == 0) wmin[tid >> 5] = m;
    __syncthreads();
    if (tid < 8) {
        float v = wmin[tid];
#pragma unroll
        for (int o = 4; o; o >>= 1) v = fminf(v, __shfl_xor_sync(0x000000ffu, v, o));
        if (tid == 0) wmin[0] = v;
    }
    __syncthreads();
    const float bmin = wmin[0];

    for (int i = tid; i < NN; i += 256) {
        float x = lp[i] - bmin;
        float w = 2.0f / (1.0f + expf(30.0f * x));
        out[b * NN + i] = (w > 0.6f) ? 1.0f : 0.0f;
    }
}

// ---------------------------------------------------------------------------
extern "C" void kernel_launch(void* const* d_in, const int* in_sizes, int n_in,
                              void* d_out, int out_size) {
    const float* src = (const float*)d_in[0];
    const float* tgt = (const float*)d_in[1];
    float* out = (float*)d_out;

    knn_kernel <<<BB * (NN / K1_BLK), K1_BLK>>>(src);
    loss_kernel<<<BB * (NN / K2_BLK), K2_BLK>>>(src, tgt);
    weight_kernel<<<BB, 256>>>(out);
}

// round 2
// speedup vs baseline: 1.8037x; 1.8037x over previous
#include <cuda_runtime.h>

#define BB 16
#define NN 2048
#define KK 10
#define FULLM 0xffffffffu

__device__ int   g_idx[BB * NN * KK];
__device__ float g_loss[BB * NN];

// ---------------------------------------------------------------------------
// Kernel 1: warp-per-query masked KNN.
// Top-10 keys held one-per-lane (lanes 0..9 = sorted top-10, rest = MAX pad).
// Key = (float_bits(d2 + 1e-7) << 32) | candidate_index  (exact stable top_k).
// ---------------------------------------------------------------------------
__global__ void __launch_bounds__(512) knn_kernel(const float* __restrict__ src) {
    __shared__ float4 sp[NN];
    const int b     = blockIdx.x >> 7;   // 128 blocks per batch
    const int chunk = blockIdx.x & 127;
    const float* base = src + (size_t)b * 3 * NN;

    for (int i = threadIdx.x; i < NN; i += 512) {
        float x = base[i];
        float y = base[NN + i];
        float z = base[2 * NN + i];
        sp[i] = make_float4(x, y, z, x * x + y * y + z * z);
    }
    __syncthreads();

    const int warp = threadIdx.x >> 5;
    const int lane = threadIdx.x & 31;
    const int q    = chunk * 16 + warp;

    const float4 Q = sp[q];

    unsigned long long key = ~0ULL;       // this lane's slot in the sorted list
    unsigned tau = 0xFFFFFFFFu;           // float bits of current 10th-best d2f

#pragma unroll 2
    for (int batch = 0; batch < NN / 32; batch++) {
        const int i = batch * 32 + lane;
        float4 p = sp[i];
        float dot = Q.x * p.x + Q.y * p.y + Q.z * p.z;
        float d2f = (Q.w + p.w - 2.0f * dot) + 1e-7f;   // ref: d2 + 1e-7
        unsigned du = __float_as_uint(d2f);
        // ref mask: excluded iff -(d2+1e-7) > -0.1  <=>  d2f < 0.1
        bool pred = (d2f >= 0.1f) && (du <= tau);       // <= : exact float ties go through key cmp
        unsigned m = __ballot_sync(FULLM, pred);

        while (m) {
            int s = __ffs(m) - 1;
            m &= m - 1;
            unsigned kb = __shfl_sync(FULLM, du, s);
            unsigned long long k =
                ((unsigned long long)kb << 32) | (unsigned)(batch * 32 + s);
            unsigned long long up = __shfl_up_sync(FULLM, key, 1);
            bool c = (k < key);
            unsigned long long ins = (lane == 0 || up <= k) ? k : up;
            key = c ? ins : key;
        }
        tau = __shfl_sync(FULLM, (unsigned)(key >> 32), 9);
    }

    int* op = g_idx + ((size_t)(b * NN) + q) * KK;

    // valid (non-MAX) slots among lanes 0..9
    unsigned vm = __ballot_sync(FULLM, key != ~0ULL) & 0x3FFu;
    int cnt = __popc(vm);
    if (lane < cnt) op[lane] = (int)(unsigned)key;

    // Rare fallback: fewer than 10 valid neighbors -> top_k fills with the
    // smallest masked indices (all tied at -inf).
    if (cnt < KK && lane == 0) {
        int slot = cnt;
        for (int i = 0; i < NN && slot < KK; i++) {
            float4 p = sp[i];
            float dot = Q.x * p.x + Q.y * p.y + Q.z * p.z;
            float d2f = (Q.w + p.w - 2.0f * dot) + 1e-7f;
            if (!(d2f >= 0.1f)) op[slot++] = i;
        }
    }
}

// ---------------------------------------------------------------------------
// Kernel 2: 45 triangle pair losses per point, mean of sqrt of 10 smallest
// ---------------------------------------------------------------------------
__device__ __forceinline__ void sort3(float& a, float& b, float& c) {
    float t0 = fminf(a, b), t1 = fmaxf(a, b);
    float hi = fmaxf(t1, c);
    float mm = fminf(t1, c);
    float lo = fminf(t0, mm);
    float mi = fmaxf(t0, mm);
    a = lo; b = mi; c = hi;
}

#define K2_BLK 256

__global__ void __launch_bounds__(K2_BLK) loss_kernel(const float* __restrict__ src,
                                                      const float* __restrict__ tgt) {
    __shared__ float ssx[NN], ssy[NN], ssz[NN];
    __shared__ float stx[NN], sty[NN], stz[NN];
    const int blocksPerB = NN / K2_BLK;
    const int b     = blockIdx.x / blocksPerB;
    const int chunk = blockIdx.x % blocksPerB;
    const float* sb = src + (size_t)b * 3 * NN;
    const float* tb = tgt + (size_t)b * 3 * NN;

    for (int i = threadIdx.x; i < NN; i += K2_BLK) {
        ssx[i] = sb[i]; ssy[i] = sb[NN + i]; ssz[i] = sb[2 * NN + i];
        stx[i] = tb[i]; sty[i] = tb[NN + i]; stz[i] = tb[2 * NN + i];
    }
    __syncthreads();

    const int n = chunk * K2_BLK + threadIdx.x;
    const int* nb = g_idx + ((size_t)(b * NN) + n) * KK;

    float px[KK + 1], py[KK + 1], pz[KK + 1];
    float tx[KK + 1], ty[KK + 1], tz[KK + 1];
    px[0] = ssx[n]; py[0] = ssy[n]; pz[0] = ssz[n];
    tx[0] = stx[n]; ty[0] = sty[n]; tz[0] = stz[n];
#pragma unroll
    for (int j = 0; j < KK; j++) {
        int m = nb[j];
        px[j + 1] = ssx[m]; py[j + 1] = ssy[m]; pz[j + 1] = ssz[m];
        tx[j + 1] = stx[m]; ty[j + 1] = sty[m]; tz[j + 1] = stz[m];
    }

    const float INF = __int_as_float(0x7f800000);
    float ls[KK];
#pragma unroll
    for (int j = 0; j < KK; j++) ls[j] = INF;
    float worst = INF;

#pragma unroll
    for (int a = 0; a < KK - 1; a++) {
#pragma unroll
        for (int c = a + 1; c < KK; c++) {
            const int ia = a + 1, ic = c + 1;
            float dx, dy, dz;
            dx = px[0] - px[ia]; dy = py[0] - py[ia]; dz = pz[0] - pz[ia];
            float s01 = dx * dx + dy * dy + dz * dz;
            dx = px[ia] - px[ic]; dy = py[ia] - py[ic]; dz = pz[ia] - pz[ic];
            float s12 = dx * dx + dy * dy + dz * dz;
            dx = px[0] - px[ic]; dy = py[0] - py[ic]; dz = pz[0] - pz[ic];
            float s02 = dx * dx + dy * dy + dz * dz;
            sort3(s01, s12, s02);
            dx = tx[0] - tx[ia]; dy = ty[0] - ty[ia]; dz = tz[0] - tz[ia];
            float t01 = dx * dx + dy * dy + dz * dz;
            dx = tx[ia] - tx[ic]; dy = ty[ia] - ty[ic]; dz = tz[ia] - tz[ic];
            float t12 = dx * dx + dy * dy + dz * dz;
            dx = tx[0] - tx[ic]; dy = ty[0] - ty[ic]; dz = tz[0] - tz[ic];
            float t02 = dx * dx + dy * dy + dz * dz;
            sort3(t01, t12, t02);
            t01 += 1e-6f; t12 += 1e-6f; t02 += 1e-6f;

            float n0 = s01 - t01, n1 = s12 - t12, n2 = s02 - t02;
            float num = n0 * n0 + n1 * n1 + n2 * n2;
            float p0 = s01 + t01, p1 = s12 + t12, p2 = s02 + t02;
            float den = p0 * p0 + p1 * p1 + p2 * p2;
            float L = num / den;

            if (L < worst) {
                float cd = L;
#pragma unroll
                for (int j = 0; j < KK; j++) {
                    if (cd < ls[j]) { float t = ls[j]; ls[j] = cd; cd = t; }
                }
                worst = ls[KK - 1];
            }
        }
    }

    float acc = 0.0f;
#pragma unroll
    for (int j = 0; j < KK; j++) acc += sqrtf(ls[j] + 1e-6f);
    g_loss[b * NN + n] = acc * 0.1f;
}

// ---------------------------------------------------------------------------
// Kernel 3: per-batch min, sigmoid weight, threshold
// ---------------------------------------------------------------------------
__global__ void __launch_bounds__(256) weight_kernel(float* __restrict__ out) {
    const int b   = blockIdx.x;
    const int tid = threadIdx.x;
    const float* lp = g_loss + b * NN;

    float m = __int_as_float(0x7f800000);
    for (int i = tid; i < NN; i += 256) m = fminf(m, lp[i]);
#pragma unroll
    for (int o = 16; o; o >>= 1) m = fminf(m, __shfl_xor_sync(0xffffffffu, m, o));

    __shared__ float wmin[8];
    if ((tid & 31) == 0) wmin[tid >> 5] = m;
    __syncthreads();
    if (tid < 8) {
        float v = wmin[tid];
#pragma unroll
        for (int o = 4; o; o >>= 1) v = fminf(v, __shfl_xor_sync(0x000000ffu, v, o));
        if (tid == 0) wmin[0] = v;
    }
    __syncthreads();
    const float bmin = wmin[0];

    for (int i = tid; i < NN; i += 256) {
        float x = lp[i] - bmin;
        float w = 2.0f / (1.0f + expf(30.0f * x));
        out[b * NN + i] = (w > 0.6f) ? 1.0f : 0.0f;
    }
}

// ---------------------------------------------------------------------------
extern "C" void kernel_launch(void* const* d_in, const int* in_sizes, int n_in,
                              void* d_out, int out_size) {
    const float* src = (const float*)d_in[0];
    const float* tgt = (const float*)d_in[1];
    float* out = (float*)d_out;

    knn_kernel <<<BB * (NN / 16), 512>>>(src);
    loss_kernel<<<BB * (NN / K2_BLK), K2_BLK>>>(src, tgt);
    weight_kernel<<<BB, 256>>>(out);
}